// round 1
// baseline (speedup 1.0000x reference)
#include <cuda_runtime.h>

#define NB 64
#define NK 5
#define ND 1024
#define NH 32
#define NW 32
#define NHW (NH * NW)
#define GP 16            // patches per block in sims_kernel

// scratch: sims[b][k][n]  (1.25 MB) — device global per allocation rules
__device__ float g_sims[(size_t)NB * NK * NHW];

// ---------------------------------------------------------------------------
// Kernel 1: for each patch n of batch b compute sims[b][k][n] =
//           dot(cue[b][k], patch) * rsqrt(||patch||^2)
// (cue normalization is a positive per-k scale -> argmax-invariant, skipped)
// ---------------------------------------------------------------------------
__global__ void __launch_bounds__(256) sims_kernel(const float* __restrict__ cue,
                                                   const float* __restrict__ patches)
{
    const int b   = blockIdx.x / (NHW / GP);
    const int n0  = (blockIdx.x % (NHW / GP)) * GP;
    const int tid = threadIdx.x;              // 256 threads, thread t owns dims [4t,4t+4)
    const int lane = tid & 31, warp = tid >> 5;

    // cue slices into registers (loaded once per block, coalesced float4)
    float4 c[NK];
#pragma unroll
    for (int k = 0; k < NK; k++)
        c[k] = ((const float4*)(cue + ((size_t)b * NK + k) * ND))[tid];

    const float4* pb = (const float4*)(patches + (size_t)b * NHW * ND);

    __shared__ float s_part[6][8];
    __shared__ float s_fin[6];

    // software pipeline: keep next patch load in flight across the reduction
    float4 v = pb[(size_t)n0 * (ND / 4) + tid];

    for (int p = 0; p < GP; p++) {
        float4 vn = v;
        if (p + 1 < GP)
            vn = pb[(size_t)(n0 + p + 1) * (ND / 4) + tid];

        float acc[6];
        acc[5] = v.x * v.x + v.y * v.y + v.z * v.z + v.w * v.w;
#pragma unroll
        for (int k = 0; k < NK; k++)
            acc[k] = v.x * c[k].x + v.y * c[k].y + v.z * c[k].z + v.w * c[k].w;

        // warp reduction of all 6 partials
#pragma unroll
        for (int j = 0; j < 6; j++) {
#pragma unroll
            for (int off = 16; off; off >>= 1)
                acc[j] += __shfl_xor_sync(0xffffffffu, acc[j], off);
        }
        if (lane < 6) s_part[lane][warp] = acc[lane];
        __syncthreads();
        if (tid < 6) {
            float s = 0.f;
#pragma unroll
            for (int w = 0; w < 8; w++) s += s_part[tid][w];
            s_fin[tid] = s;
        }
        __syncthreads();
        if (tid < NK)
            g_sims[((size_t)b * NK + tid) * NHW + (n0 + p)] = s_fin[tid] * rsqrtf(s_fin[5]);

        v = vn;
    }
}

// ---------------------------------------------------------------------------
// Kernel 2: per (b,k): first-index argmax over 1024 sims, then zero-padded
//           3x3 neighborhood mean of raw patches -> out[b][k][:]
// ---------------------------------------------------------------------------
__global__ void __launch_bounds__(256) argmax_gather_kernel(const float* __restrict__ patches,
                                                            float* __restrict__ out)
{
    const int bk  = blockIdx.x;       // 0..NB*NK-1
    const int b   = bk / NK;
    const int tid = threadIdx.x;
    const int lane = tid & 31, warp = tid >> 5;

    const float* s = g_sims + (size_t)bk * NHW;

    // per-thread scan (indices strictly increasing -> strict '>' keeps first max)
    float bestv = -3.402823466e+38f;
    int   besti = 0;
#pragma unroll
    for (int i = 0; i < NHW / 256; i++) {
        int n = tid + i * 256;
        float val = s[n];
        if (val > bestv) { bestv = val; besti = n; }
    }
    // warp reduce with first-index tie-break
#pragma unroll
    for (int off = 16; off; off >>= 1) {
        float ov = __shfl_xor_sync(0xffffffffu, bestv, off);
        int   oi = __shfl_xor_sync(0xffffffffu, besti, off);
        if (ov > bestv || (ov == bestv && oi < besti)) { bestv = ov; besti = oi; }
    }
    __shared__ float sv[8];
    __shared__ int   si[8];
    __shared__ int   s_idx;
    if (lane == 0) { sv[warp] = bestv; si[warp] = besti; }
    __syncthreads();
    if (tid == 0) {
        float bv = sv[0]; int bi = si[0];
#pragma unroll
        for (int w = 1; w < 8; w++)
            if (sv[w] > bv || (sv[w] == bv && si[w] < bi)) { bv = sv[w]; bi = si[w]; }
        s_idx = bi;
    }
    __syncthreads();

    const int idx = s_idx;
    const int r = idx >> 5;       // row in [0,32)
    const int cc0 = idx & 31;     // col in [0,32)

    const float4* pb = (const float4*)(patches + (size_t)b * NHW * ND);
    float4 acc = make_float4(0.f, 0.f, 0.f, 0.f);
#pragma unroll
    for (int dy = -1; dy <= 1; dy++) {
        int rr = r + dy;
        if (rr < 0 || rr >= NH) continue;
#pragma unroll
        for (int dx = -1; dx <= 1; dx++) {
            int cc = cc0 + dx;
            if (cc < 0 || cc >= NW) continue;
            float4 t = pb[(size_t)(rr * NW + cc) * (ND / 4) + tid];
            acc.x += t.x; acc.y += t.y; acc.z += t.z; acc.w += t.w;
        }
    }
    const float inv9 = 1.0f / 9.0f;
    acc.x *= inv9; acc.y *= inv9; acc.z *= inv9; acc.w *= inv9;
    ((float4*)out)[(size_t)bk * (ND / 4) + tid] = acc;
}

// ---------------------------------------------------------------------------
extern "C" void kernel_launch(void* const* d_in, const int* in_sizes, int n_in,
                              void* d_out, int out_size)
{
    const float* cue     = (const float*)d_in[0];   // (64,5,1024)
    const float* patches = (const float*)d_in[1];   // (64,32,32,1024)
    float*       out     = (float*)d_out;           // (64,5,1024)

    (void)in_sizes; (void)n_in; (void)out_size;

    sims_kernel<<<NB * (NHW / GP), 256>>>(cue, patches);
    argmax_gather_kernel<<<NB * NK, 256>>>(patches, out);
}

// round 2
// speedup vs baseline: 1.5477x; 1.5477x over previous
#include <cuda_runtime.h>
#include <float.h>

#define NB 64
#define NK 5
#define ND 1024
#define NH 32
#define NW 32
#define NHW (NH * NW)

// scratch (device globals per allocation rules)
__device__ float g_sims[(size_t)NB * NK * NHW];   // 1.25 MB
__device__ int   g_idx[NB * NK];

// ---------------------------------------------------------------------------
// Kernel 1: sims[b][k][n] = dot(cue[b][k], patch[b][n]) * rsqrt(||patch||^2)
// (cue normalization is a positive per-k scale -> argmax-invariant, skipped)
// Warp-autonomous: each warp handles 4 patches end-to-end, no block barriers
// in the hot loop. Lane owns float4 column (u*32 + lane), u = 0..7.
// ---------------------------------------------------------------------------
__global__ void __launch_bounds__(256, 2) sims_kernel(const float* __restrict__ cue,
                                                      const float* __restrict__ patches)
{
    const int b    = blockIdx.x >> 5;          // 32 groups of 32 patches per b
    const int g    = blockIdx.x & 31;
    const int warp = threadIdx.x >> 5;
    const int lane = threadIdx.x & 31;

    __shared__ float s_cue[NK * ND];           // 20 KB

    // stage cue[b] into smem once
    {
        const float4* cs = (const float4*)(cue + (size_t)b * NK * ND);
        float4* sd = (float4*)s_cue;
#pragma unroll
        for (int i = 0; i < (NK * ND / 4) / 256; i++)
            sd[threadIdx.x + i * 256] = cs[threadIdx.x + i * 256];
        // remainder: NK*ND/4 = 1280 = 5*256, exact
    }
    __syncthreads();

    const int p0 = g * 32 + warp * 4;          // this warp's 4 patches
    const float4* pbase = (const float4*)(patches + ((size_t)b * NHW + p0) * ND);

    float acc[4][6];
#pragma unroll
    for (int p = 0; p < 4; p++)
#pragma unroll
        for (int j = 0; j < 6; j++) acc[p][j] = 0.f;

    // double-buffered patch chunk loads: v[buf][p]
    float4 v[2][4];
#pragma unroll
    for (int p = 0; p < 4; p++)
        v[0][p] = pbase[(size_t)p * (ND / 4) + lane];

#pragma unroll
    for (int u = 0; u < 8; u++) {
        const int cur = u & 1;
        if (u < 7) {
#pragma unroll
            for (int p = 0; p < 4; p++)
                v[cur ^ 1][p] = pbase[(size_t)p * (ND / 4) + (u + 1) * 32 + lane];
        }
        // cue chunk (conflict-free float4 LDS)
        float4 c[NK];
#pragma unroll
        for (int k = 0; k < NK; k++)
            c[k] = ((const float4*)(s_cue + k * ND))[u * 32 + lane];

#pragma unroll
        for (int p = 0; p < 4; p++) {
            const float4 t = v[cur][p];
            acc[p][5] += t.x * t.x + t.y * t.y + t.z * t.z + t.w * t.w;
#pragma unroll
            for (int k = 0; k < NK; k++)
                acc[p][k] += t.x * c[k].x + t.y * c[k].y + t.z * c[k].z + t.w * c[k].w;
        }
    }

    // butterfly all-reduce of the 24 partials (each lane ends with full sums)
#pragma unroll
    for (int p = 0; p < 4; p++)
#pragma unroll
        for (int j = 0; j < 6; j++) {
#pragma unroll
            for (int off = 16; off; off >>= 1)
                acc[p][j] += __shfl_xor_sync(0xffffffffu, acc[p][j], off);
        }

    // lanes 0..19 each emit one (p,k)
    float outv = 0.f, nrm = 1.f;
#pragma unroll
    for (int p = 0; p < 4; p++)
#pragma unroll
        for (int k = 0; k < NK; k++)
            if (lane == p * NK + k) { outv = acc[p][k]; nrm = acc[p][5]; }

    if (lane < 4 * NK) {
        const int p = lane / NK, k = lane % NK;
        g_sims[((size_t)b * NK + k) * NHW + (p0 + p)] = outv * rsqrtf(nrm);
    }
}

// ---------------------------------------------------------------------------
// Kernel 2a: warp-per-(b,k) first-index argmax over 1024 sims
// ---------------------------------------------------------------------------
__global__ void __launch_bounds__(256) argmax_kernel()
{
    const int w    = (blockIdx.x * 256 + threadIdx.x) >> 5;   // bk, 0..319 exact
    const int lane = threadIdx.x & 31;

    const float* s = g_sims + (size_t)w * NHW;
    float bv = -FLT_MAX;
    int   bi = 0;
#pragma unroll
    for (int i = 0; i < NHW / 32; i++) {
        const int n = lane + i * 32;       // per-lane increasing -> '>' keeps first
        const float val = s[n];
        if (val > bv) { bv = val; bi = n; }
    }
#pragma unroll
    for (int off = 16; off; off >>= 1) {
        const float ov = __shfl_xor_sync(0xffffffffu, bv, off);
        const int   oi = __shfl_xor_sync(0xffffffffu, bi, off);
        if (ov > bv || (ov == bv && oi < bi)) { bv = ov; bi = oi; }
    }
    if (lane == 0) g_idx[w] = bi;
}

// ---------------------------------------------------------------------------
// Kernel 2b: zero-padded 3x3 neighborhood mean around g_idx[bk]
// ---------------------------------------------------------------------------
__global__ void __launch_bounds__(256) gather_kernel(const float* __restrict__ patches,
                                                     float* __restrict__ out)
{
    const int bk  = blockIdx.x;
    const int b   = bk / NK;
    const int tid = threadIdx.x;

    const int idx = g_idx[bk];
    const int r   = idx >> 5;
    const int cc0 = idx & 31;

    const float4* pb = (const float4*)(patches + (size_t)b * NHW * ND);
    float4 acc = make_float4(0.f, 0.f, 0.f, 0.f);
#pragma unroll
    for (int dy = -1; dy <= 1; dy++) {
        const int rr = r + dy;
        if (rr < 0 || rr >= NH) continue;
#pragma unroll
        for (int dx = -1; dx <= 1; dx++) {
            const int cc = cc0 + dx;
            if (cc < 0 || cc >= NW) continue;
            const float4 t = pb[(size_t)(rr * NW + cc) * (ND / 4) + tid];
            acc.x += t.x; acc.y += t.y; acc.z += t.z; acc.w += t.w;
        }
    }
    const float inv9 = 1.0f / 9.0f;
    acc.x *= inv9; acc.y *= inv9; acc.z *= inv9; acc.w *= inv9;
    ((float4*)out)[(size_t)bk * (ND / 4) + tid] = acc;
}

// ---------------------------------------------------------------------------
extern "C" void kernel_launch(void* const* d_in, const int* in_sizes, int n_in,
                              void* d_out, int out_size)
{
    const float* cue     = (const float*)d_in[0];   // (64,5,1024)
    const float* patches = (const float*)d_in[1];   // (64,32,32,1024)
    float*       out     = (float*)d_out;           // (64,5,1024)

    (void)in_sizes; (void)n_in; (void)out_size;

    sims_kernel<<<NB * 32, 256>>>(cue, patches);    // 2048 blocks, 32 patches each
    argmax_kernel<<<(NB * NK) / 8, 256>>>();        // 40 blocks, warp per (b,k)
    gather_kernel<<<NB * NK, 256>>>(patches, out);  // 320 blocks
}

// round 3
// speedup vs baseline: 1.5848x; 1.0240x over previous
#include <cuda_runtime.h>
#include <float.h>

#define NB 64
#define NK 5
#define ND 1024
#define NH 32
#define NW 32
#define NHW (NH * NW)

#define GRID1 304                       // 2 CTAs/SM on GB300 (152 SMs) -> one wave
#define NTASK (NB * NHW / 4)            // 16384 tasks of 4 patches each

// scratch (device globals per allocation rules)
__device__ float g_sims[(size_t)NB * NK * NHW];   // 1.25 MB
__device__ int   g_idx[NB * NK];

// ---------------------------------------------------------------------------
// Kernel 1 (persistent, single wave):
//   sims[b][k][n] = dot(cue[b][k], patch[b][n]) * rsqrt(||patch||^2)
// (cue normalization is a positive per-k scale -> argmax-invariant, skipped)
// Block owns a contiguous task range; warp processes 4 patches per task with
// double-buffered chunk loads and cross-task prefetch. No barriers in the
// steady loop.
// ---------------------------------------------------------------------------
__global__ void __launch_bounds__(256, 2) sims_kernel(const float* __restrict__ cue,
                                                      const float* __restrict__ patches)
{
    const int w    = blockIdx.x;
    const int t0   = (int)(((long long)w * NTASK) / GRID1);
    const int t1   = (int)(((long long)(w + 1) * NTASK) / GRID1);
    const int warp = threadIdx.x >> 5;
    const int lane = threadIdx.x & 31;

    const int b0 = t0 >> 8;                        // 256 tasks per batch b
    __shared__ float s_cue[2 * NK * ND];           // 40 KB: cue for b0 (and b0+1)

    // stage cue once per block lifetime (range spans at most 2 b values)
    {
        const int nb = (((t1 - 1) >> 8) != b0) ? 2 : 1;
        const float4* cs = (const float4*)(cue + (size_t)b0 * NK * ND);
        float4* sd = (float4*)s_cue;
        for (int i = threadIdx.x; i < nb * (NK * ND / 4); i += 256)
            sd[i] = cs[i];
    }
    __syncthreads();

    const float4* patches4 = (const float4*)patches;

    int t = t0 + warp;                             // this warp's first task
    if (t >= t1) return;

    size_t base = (size_t)t * (4 * ND / 4);        // float4 offset of task's 4 patches
    float4 v[2][4];
#pragma unroll
    for (int p = 0; p < 4; p++)
        v[0][p] = patches4[base + (size_t)p * (ND / 4) + lane];

    for (;;) {
        const float* cs = s_cue + ((t >> 8) - b0) * (NK * ND);

        const int tn = t + 8;                      // next task (warp stride 8)
        const bool has_next = (tn < t1);
        const size_t nbase = (size_t)tn * (4 * ND / 4);

        float acc[4][6];
#pragma unroll
        for (int p = 0; p < 4; p++)
#pragma unroll
            for (int j = 0; j < 6; j++) acc[p][j] = 0.f;

#pragma unroll
        for (int u = 0; u < 8; u++) {
            const int cur = u & 1;
            if (u < 7) {
#pragma unroll
                for (int p = 0; p < 4; p++)
                    v[cur ^ 1][p] = patches4[base + (size_t)p * (ND / 4) + (u + 1) * 32 + lane];
            } else if (has_next) {
                // cross-task prefetch: keep loads in flight through the reduction
#pragma unroll
                for (int p = 0; p < 4; p++)
                    v[cur ^ 1][p] = patches4[nbase + (size_t)p * (ND / 4) + lane];
            }
            float4 c[NK];
#pragma unroll
            for (int k = 0; k < NK; k++)
                c[k] = ((const float4*)(cs + k * ND))[u * 32 + lane];

#pragma unroll
            for (int p = 0; p < 4; p++) {
                const float4 x = v[cur][p];
                acc[p][5] += x.x * x.x + x.y * x.y + x.z * x.z + x.w * x.w;
#pragma unroll
                for (int k = 0; k < NK; k++)
                    acc[p][k] += x.x * c[k].x + x.y * c[k].y + x.z * c[k].z + x.w * c[k].w;
            }
        }

        // butterfly all-reduce of the 24 partials (runs under the prefetch)
#pragma unroll
        for (int p = 0; p < 4; p++)
#pragma unroll
            for (int j = 0; j < 6; j++) {
#pragma unroll
                for (int off = 16; off; off >>= 1)
                    acc[p][j] += __shfl_xor_sync(0xffffffffu, acc[p][j], off);
            }

        // lanes 0..19 each emit one (p,k); static selection to keep regs
        float outv = 0.f, nrm = 1.f;
#pragma unroll
        for (int p = 0; p < 4; p++)
#pragma unroll
            for (int k = 0; k < NK; k++)
                if (lane == p * NK + k) { outv = acc[p][k]; nrm = acc[p][5]; }

        if (lane < 4 * NK) {
            const int p  = lane / NK, k = lane % NK;
            const int bb = t >> 8;
            const int n0 = (t & 255) * 4;
            g_sims[((size_t)bb * NK + k) * NHW + (n0 + p)] = outv * rsqrtf(nrm);
        }

        if (!has_next) break;
        t = tn;
        base = nbase;                               // v[0] already holds tn's chunk 0
    }
}

// ---------------------------------------------------------------------------
// Kernel 2a: warp-per-(b,k) first-index argmax over 1024 sims (L2-resident)
// ---------------------------------------------------------------------------
__global__ void __launch_bounds__(256) argmax_kernel()
{
    const int w    = (blockIdx.x * 256 + threadIdx.x) >> 5;   // bk, 0..319
    const int lane = threadIdx.x & 31;

    const float* s = g_sims + (size_t)w * NHW;
    float bv = -FLT_MAX;
    int   bi = 0;
#pragma unroll
    for (int i = 0; i < NHW / 32; i++) {
        const int n = lane + i * 32;       // per-lane increasing -> '>' keeps first
        const float val = s[n];
        if (val > bv) { bv = val; bi = n; }
    }
#pragma unroll
    for (int off = 16; off; off >>= 1) {
        const float ov = __shfl_xor_sync(0xffffffffu, bv, off);
        const int   oi = __shfl_xor_sync(0xffffffffu, bi, off);
        if (ov > bv || (ov == bv && oi < bi)) { bv = ov; bi = oi; }
    }
    if (lane == 0) g_idx[w] = bi;
}

// ---------------------------------------------------------------------------
// Kernel 2b: zero-padded 3x3 neighborhood mean around g_idx[bk]
// ---------------------------------------------------------------------------
__global__ void __launch_bounds__(256) gather_kernel(const float* __restrict__ patches,
                                                     float* __restrict__ out)
{
    const int bk  = blockIdx.x;
    const int b   = bk / NK;
    const int tid = threadIdx.x;

    const int idx = g_idx[bk];
    const int r   = idx >> 5;
    const int cc0 = idx & 31;

    const float4* pb = (const float4*)(patches + (size_t)b * NHW * ND);
    float4 acc = make_float4(0.f, 0.f, 0.f, 0.f);
#pragma unroll
    for (int dy = -1; dy <= 1; dy++) {
        const int rr = r + dy;
        if (rr < 0 || rr >= NH) continue;
#pragma unroll
        for (int dx = -1; dx <= 1; dx++) {
            const int cc = cc0 + dx;
            if (cc < 0 || cc >= NW) continue;
            const float4 q = pb[(size_t)(rr * NW + cc) * (ND / 4) + tid];
            acc.x += q.x; acc.y += q.y; acc.z += q.z; acc.w += q.w;
        }
    }
    const float inv9 = 1.0f / 9.0f;
    acc.x *= inv9; acc.y *= inv9; acc.z *= inv9; acc.w *= inv9;
    ((float4*)out)[(size_t)bk * (ND / 4) + tid] = acc;
}

// ---------------------------------------------------------------------------
extern "C" void kernel_launch(void* const* d_in, const int* in_sizes, int n_in,
                              void* d_out, int out_size)
{
    const float* cue     = (const float*)d_in[0];   // (64,5,1024)
    const float* patches = (const float*)d_in[1];   // (64,32,32,1024)
    float*       out     = (float*)d_out;           // (64,5,1024)

    (void)in_sizes; (void)n_in; (void)out_size;

    sims_kernel<<<GRID1, 256>>>(cue, patches);       // persistent, single wave
    argmax_kernel<<<(NB * NK) / 8, 256>>>();         // 40 blocks, warp per (b,k)
    gather_kernel<<<NB * NK, 256>>>(patches, out);   // 320 blocks
}